// round 14
// baseline (speedup 1.0000x reference)
#include <cuda_runtime.h>
#include <cuda_fp16.h>
#include <cstdint>

#define SEQ    3072
#define HID    1280
#define NHEAD  16
#define HD     80
#define SEGLEN 512
#define NSEG   6
#define QKVN   3840

// ---------------- scratch (no allocations allowed) ----------------
// q/k stored in INTERLEAVED-PAIR dim order (2d, 2d+1) = rotated (d, d+40);
// QK^T is invariant since q and k share the permutation. v in true order.
__device__ __half g_q[NHEAD * SEQ * HD];
__device__ __half g_k[NHEAD * SEQ * HD];
__device__ __half g_v[NHEAD * SEQ * HD];
__device__ __half g_attn16[SEQ * HID];

__device__ __half g_a16[SEQ * HID];
__device__ __half g_wqkv16[QKVN * HID];        // Q/K rows permuted (rope pairs adjacent)
__device__ float  g_bqkv[QKVN];
__device__ __half g_wpr16[HID * HID];

// ---------------- helpers ----------------
__device__ __forceinline__ void cp16(void* dst, const void* src)
{
    unsigned d = (unsigned)__cvta_generic_to_shared(dst);
    asm volatile("cp.async.cg.shared.global [%0], [%1], 16;" :: "r"(d), "l"(src));
}

__device__ __forceinline__ void mma_f16(
    float& c0, float& c1, float& c2, float& c3,
    unsigned a0, unsigned a1, unsigned a2, unsigned a3,
    unsigned b0, unsigned b1)
{
    asm volatile(
        "mma.sync.aligned.m16n8k16.row.col.f32.f16.f16.f32 "
        "{%0,%1,%2,%3}, {%4,%5,%6,%7}, {%8,%9}, {%0,%1,%2,%3};"
        : "+f"(c0), "+f"(c1), "+f"(c2), "+f"(c3)
        : "r"(a0), "r"(a1), "r"(a2), "r"(a3), "r"(b0), "r"(b1));
}

__device__ __forceinline__ void ldsm_x4(unsigned* r, const void* p)
{
    unsigned addr = (unsigned)__cvta_generic_to_shared(p);
    asm volatile("ldmatrix.sync.aligned.m8n8.x4.shared.b16 {%0,%1,%2,%3}, [%4];"
                 : "=r"(r[0]), "=r"(r[1]), "=r"(r[2]), "=r"(r[3]) : "r"(addr));
}
__device__ __forceinline__ void ldsm_x4t(unsigned* r, const void* p)
{
    unsigned addr = (unsigned)__cvta_generic_to_shared(p);
    asm volatile("ldmatrix.sync.aligned.m8n8.x4.trans.shared.b16 {%0,%1,%2,%3}, [%4];"
                 : "=r"(r[0]), "=r"(r[1]), "=r"(r[2]), "=r"(r[3]) : "r"(addr));
}

__device__ __forceinline__ unsigned packh2(float a, float b)
{
    __half2 h = __floats2half2_rn(a, b);
    return *(unsigned*)&h;
}

// ---------------- merged prep kernel (all casts in one launch) ----------------
#define PREP_NA ((SEQ * HID / 4) / 256)          // 3840
#define PREP_NB ((QKVN * HID / 4) / 256)         // 4800
#define PREP_NC ((HID * HID / 4) / 256)          // 1600

__global__ __launch_bounds__(256) void prep_kernel(
    const float* __restrict__ hidden, const float* __restrict__ w_qkv,
    const float* __restrict__ b_qkv,  const float* __restrict__ w_proj,
    __half* __restrict__ a16, __half* __restrict__ wqkv16,
    float* __restrict__ bqkv, __half* __restrict__ wpr16)
{
    const int gb = blockIdx.x;
    if (gb < PREP_NA) {
        int i = gb * 256 + threadIdx.x;
        float4 x = ((const float4*)hidden)[i];
        ((__half2*)a16)[i * 2]     = __floats2half2_rn(x.x, x.y);
        ((__half2*)a16)[i * 2 + 1] = __floats2half2_rn(x.z, x.w);
    } else if (gb < PREP_NA + PREP_NB) {
        if (gb == PREP_NA) {
            for (int n = threadIdx.x; n < QKVN; n += 256) {
                int reg = n / HID, cc = n % HID;
                int h = cc / 80, j = cc % 80;
                int old = (reg < 2) ? reg * HID + h * 80 + (j >> 1) + (j & 1) * 40 : n;
                bqkv[n] = b_qkv[old];
            }
        }
        int i = (gb - PREP_NA) * 256 + threadIdx.x;
        int nr   = i / (HID / 4);
        int col4 = (i % (HID / 4)) * 4;
        int reg = nr / HID, cc = nr % HID;
        int h = cc / 80, j = cc % 80;
        int old = (reg < 2) ? reg * HID + h * 80 + (j >> 1) + (j & 1) * 40 : nr;
        float4 x = *(const float4*)&w_qkv[(size_t)old * HID + col4];
        __half2* o = (__half2*)&wqkv16[(size_t)nr * HID + col4];
        o[0] = __floats2half2_rn(x.x, x.y);
        o[1] = __floats2half2_rn(x.z, x.w);
    } else {
        int i = (gb - PREP_NA - PREP_NB) * 256 + threadIdx.x;
        float4 x = ((const float4*)w_proj)[i];
        ((__half2*)wpr16)[i * 2]     = __floats2half2_rn(x.x, x.y);
        ((__half2*)wpr16)[i * 2 + 1] = __floats2half2_rn(x.z, x.w);
    }
}

// ---------------- GEMM config: 128x128 block, 8 warps, 64x32 warp tile, BK=64 ----------------
// 3-stage cp.async pipeline, single barrier per k-chunk.
#define SPAD 72
#define GSTG (128 * SPAD)
#define GEMM_SMEM (2 * GSTG * 2 * 3)   // 2 arrays x 3 stages x 2B = 110592

#define PFG(k0, s) do {                                                  \
        const int st = (s) * GSTG;                                       \
        for (int i = t; i < 1024; i += 256) {                            \
            int r = i >> 3, c8 = (i & 7) * 8;                            \
            cp16(sA + st + r * SPAD + c8, A + (size_t)(bm + r) * K + (k0) + c8); \
            cp16(sB + st + r * SPAD + c8, B + (size_t)(bn + r) * K + (k0) + c8); \
        }                                                                \
        asm volatile("cp.async.commit_group;");                          \
    } while (0)

// iteration c (stage s=c%3): wait for chunk c's group (allow c+1's to float),
// barrier (visibility + proves compute(c-1) done), prefetch c+2 into (c-1)%3,
// compute stage s.
#define GEMM_MAINLOOP()                                                  \
    PFG(0, 0);                                                           \
    PFG(64, 1);                                                          \
    {                                                                    \
        int s = 0;                                                       \
        const int NCH = K / 64;                                          \
        for (int c = 0; c < NCH; c++, s = (s == 2 ? 0 : s + 1)) {        \
            if (c + 1 < NCH) asm volatile("cp.async.wait_group 1;");     \
            else             asm volatile("cp.async.wait_group 0;");     \
            __syncthreads();                                             \
            if (c + 2 < NCH) {                                           \
                const int ps = (s == 0) ? 2 : s - 1;                     \
                PFG((c + 2) * 64, ps);                                   \
            }                                                            \
            const int st = s * GSTG;                                     \
            _Pragma("unroll")                                            \
            for (int ks = 0; ks < 64; ks += 16) {                        \
                unsigned af[4][4], bq[2][4];                             \
                _Pragma("unroll")                                        \
                for (int p = 0; p < 2; p++)                              \
                    ldsm_x4(bq[p], &sB[st + (nw * 32 + p * 16 + b_row4) * SPAD + ks + b_col4]); \
                _Pragma("unroll")                                        \
                for (int mt = 0; mt < 4; mt++)                           \
                    ldsm_x4(af[mt], &sA[st + (mw * 64 + mt * 16 + a_row) * SPAD + ks + a_col]); \
                _Pragma("unroll")                                        \
                for (int mt = 0; mt < 4; mt++)                           \
                    _Pragma("unroll")                                    \
                    for (int p = 0; p < 2; p++) {                        \
                        mma_f16(acc[mt][2*p][0], acc[mt][2*p][1], acc[mt][2*p][2], acc[mt][2*p][3], \
                                af[mt][0], af[mt][1], af[mt][2], af[mt][3], \
                                bq[p][0], bq[p][1]);                     \
                        mma_f16(acc[mt][2*p+1][0], acc[mt][2*p+1][1], acc[mt][2*p+1][2], acc[mt][2*p+1][3], \
                                af[mt][0], af[mt][1], af[mt][2], af[mt][3], \
                                bq[p][2], bq[p][3]);                     \
                    }                                                    \
            }                                                            \
        }                                                                \
    }

#define GEMM_PROLOG()                                                    \
    extern __shared__ __half smg[];                                      \
    __half* sA = smg;                                                    \
    __half* sB = smg + 3 * GSTG;                                         \
    const int t    = threadIdx.x;                                        \
    const int lane = t & 31;                                             \
    const int warp = t >> 5;                                             \
    const int mw   = warp >> 2;                                          \
    const int nw   = warp & 3;                                           \
    const int bm   = blockIdx.y * 128;                                   \
    const int bn   = blockIdx.x * 128;                                   \
    float acc[4][4][4];                                                  \
    _Pragma("unroll")                                                    \
    for (int i = 0; i < 4; i++)                                          \
        _Pragma("unroll")                                                \
        for (int j = 0; j < 4; j++)                                      \
            _Pragma("unroll")                                            \
            for (int e = 0; e < 4; e++) acc[i][j][e] = 0.0f;             \
    const int a_row  = (lane & 15);                                      \
    const int a_col  = (lane >> 4) * 8;                                  \
    const int b_row4 = (lane & 7) + ((lane >> 4) & 1) * 8;               \
    const int b_col4 = ((lane >> 3) & 1) * 8;

// ---------------- QKV GEMM with fused RoPE (coalesced permuted stores) ----------------
__global__ __launch_bounds__(256, 2) void hgemm_qkv(
    const __half* __restrict__ A, const __half* __restrict__ B,
    const float* __restrict__ bias,
    const float* __restrict__ cosp, const float* __restrict__ sinp,
    __half* __restrict__ q, __half* __restrict__ k, __half* __restrict__ v,
    int N, int K)
{
    GEMM_PROLOG();
    GEMM_MAINLOOP();

#pragma unroll
    for (int mt = 0; mt < 4; mt++) {
        const int r0 = bm + mw * 64 + mt * 16 + (lane >> 2);
        const int r1 = r0 + 8;
#pragma unroll
        for (int nt = 0; nt < 4; nt++) {
            const int c = bn + nw * 32 + nt * 8 + (lane & 3) * 2;
            const float bv0 = bias[c], bv1 = bias[c + 1];
            const float a0 = acc[mt][nt][0] + bv0, a1 = acc[mt][nt][1] + bv1;
            const float a2 = acc[mt][nt][2] + bv0, a3 = acc[mt][nt][3] + bv1;
            if (c < 2560) {
                const int cc = (c < HID) ? c : c - HID;
                __half* dst = (c < HID) ? q : k;
                const int h  = cc / 80;
                const int jj = cc % 80;
                const int d  = jj >> 1;
                {
                    const float co = cosp[r0 * HD + d], sn = sinp[r0 * HD + d];
                    *(__half2*)&dst[(h * SEQ + r0) * HD + jj] =
                        __floats2half2_rn(a0 * co - a1 * sn, a1 * co + a0 * sn);
                }
                {
                    const float co = cosp[r1 * HD + d], sn = sinp[r1 * HD + d];
                    *(__half2*)&dst[(h * SEQ + r1) * HD + jj] =
                        __floats2half2_rn(a2 * co - a3 * sn, a3 * co + a2 * sn);
                }
            } else {
                const int cc = c - 2560;
                const int h = cc / 80, j = cc % 80;
                *(__half2*)&v[(h * SEQ + r0) * HD + j] = __floats2half2_rn(a0, a1);
                *(__half2*)&v[(h * SEQ + r1) * HD + j] = __floats2half2_rn(a2, a3);
            }
        }
    }
}

// ---------------- plain GEMM (proj): fp32 out ----------------
__global__ __launch_bounds__(256, 2) void hgemm_f32(
    const __half* __restrict__ A, const __half* __restrict__ B,
    const float* __restrict__ bias, float* __restrict__ C,
    int N, int K)
{
    GEMM_PROLOG();
    GEMM_MAINLOOP();

#pragma unroll
    for (int mt = 0; mt < 4; mt++) {
        const int r0 = bm + mw * 64 + mt * 16 + (lane >> 2);
        const int r1 = r0 + 8;
#pragma unroll
        for (int nt = 0; nt < 4; nt++) {
            const int c = bn + nw * 32 + nt * 8 + (lane & 3) * 2;
            const float bv0 = bias[c], bv1 = bias[c + 1];
            float2 o0 = {acc[mt][nt][0] + bv0, acc[mt][nt][1] + bv1};
            float2 o1 = {acc[mt][nt][2] + bv0, acc[mt][nt][3] + bv1};
            *(float2*)&C[(size_t)r0 * N + c] = o0;
            *(float2*)&C[(size_t)r1 * N + c] = o1;
        }
    }
}

// ---------------- flash attention ----------------
#define QPITCH 88
#define TILE_H (128 * QPITCH)
#define ATTN_SMEM (5 * TILE_H * 2)

__global__ __launch_bounds__(256, 2) void fattn_kernel(
    const __half* __restrict__ q, const __half* __restrict__ k,
    const __half* __restrict__ v, __half* __restrict__ attn_out)
{
    extern __shared__ char smraw[];
    __half* sQ = (__half*)smraw;
    __half* sK[2] = {sQ + TILE_H,     sQ + 2 * TILE_H};
    __half* sV[2] = {sQ + 3 * TILE_H, sQ + 4 * TILE_H};

    const int tid  = threadIdx.x;
    const int lane = tid & 31;
    const int w    = tid >> 5;
    const int h    = blockIdx.y;
    const int seg  = blockIdx.x >> 2;
    const int qc   = blockIdx.x & 3;
    const int qbase = seg * SEGLEN + qc * 128;
    const int kbase = seg * SEGLEN;
    const float scale = 0.11180339887498949f;

    const int a_row  = (lane & 15);
    const int a_col  = (lane >> 4) * 8;
    const int b_row4 = (lane & 7) + ((lane >> 4) & 1) * 8;
    const int b_col4 = ((lane >> 3) & 1) * 8;

    for (int i = tid; i < 1280; i += 256) {
        int r = i / 10, c8 = (i % 10) * 8;
        cp16(&sQ[r * QPITCH + c8],    &q[(size_t)(h * SEQ + qbase + r) * HD + c8]);
        cp16(&sK[0][r * QPITCH + c8], &k[(size_t)(h * SEQ + kbase + r) * HD + c8]);
        cp16(&sV[0][r * QPITCH + c8], &v[(size_t)(h * SEQ + kbase + r) * HD + c8]);
    }
    asm volatile("cp.async.commit_group;");

    float m0 = -1e30f, m1 = -1e30f, l0 = 0.0f, l1 = 0.0f;
    float oacc[10][4];
#pragma unroll
    for (int nt = 0; nt < 10; nt++)
#pragma unroll
        for (int e = 0; e < 4; e++) oacc[nt][e] = 0.0f;

    for (int kt = 0; kt < 4; kt++) {
        asm volatile("cp.async.wait_group 0;");
        __syncthreads();
        if (kt < 3) {
            const int nb = (kt + 1) & 1;
            for (int i = tid; i < 1280; i += 256) {
                int r = i / 10, c8 = (i % 10) * 8;
                cp16(&sK[nb][r * QPITCH + c8],
                     &k[(size_t)(h * SEQ + kbase + (kt + 1) * 128 + r) * HD + c8]);
                cp16(&sV[nb][r * QPITCH + c8],
                     &v[(size_t)(h * SEQ + kbase + (kt + 1) * 128 + r) * HD + c8]);
            }
            asm volatile("cp.async.commit_group;");
        }
        __half* cK = sK[kt & 1];
        __half* cV = sV[kt & 1];

#pragma unroll
        for (int hv = 0; hv < 2; hv++) {
            float s[8][4];
#pragma unroll
            for (int nt = 0; nt < 8; nt++)
#pragma unroll
                for (int e = 0; e < 4; e++) s[nt][e] = 0.0f;

#pragma unroll
            for (int ks = 0; ks < 80; ks += 16) {
                unsigned af[4];
                ldsm_x4(af, &sQ[(w * 16 + a_row) * QPITCH + ks + a_col]);
#pragma unroll
                for (int p = 0; p < 4; p++) {
                    unsigned bq[4];
                    ldsm_x4(bq, &cK[(hv * 64 + p * 16 + b_row4) * QPITCH + ks + b_col4]);
                    mma_f16(s[2*p][0], s[2*p][1], s[2*p][2], s[2*p][3],
                            af[0], af[1], af[2], af[3], bq[0], bq[1]);
                    mma_f16(s[2*p+1][0], s[2*p+1][1], s[2*p+1][2], s[2*p+1][3],
                            af[0], af[1], af[2], af[3], bq[2], bq[3]);
                }
            }

            float mx0 = -1e30f, mx1 = -1e30f;
#pragma unroll
            for (int nt = 0; nt < 8; nt++) {
                s[nt][0] *= scale; s[nt][1] *= scale;
                s[nt][2] *= scale; s[nt][3] *= scale;
                mx0 = fmaxf(mx0, fmaxf(s[nt][0], s[nt][1]));
                mx1 = fmaxf(mx1, fmaxf(s[nt][2], s[nt][3]));
            }
            mx0 = fmaxf(mx0, __shfl_xor_sync(0xffffffffu, mx0, 1));
            mx0 = fmaxf(mx0, __shfl_xor_sync(0xffffffffu, mx0, 2));
            mx1 = fmaxf(mx1, __shfl_xor_sync(0xffffffffu, mx1, 1));
            mx1 = fmaxf(mx1, __shfl_xor_sync(0xffffffffu, mx1, 2));

            const float mn0 = fmaxf(m0, mx0), mn1 = fmaxf(m1, mx1);
            const float al0 = __expf(m0 - mn0), al1 = __expf(m1 - mn1);

            float sum0 = 0.0f, sum1 = 0.0f;
            unsigned pk[8][2];
#pragma unroll
            for (int nt = 0; nt < 8; nt++) {
                float p0 = __expf(s[nt][0] - mn0);
                float p1 = __expf(s[nt][1] - mn0);
                float p2 = __expf(s[nt][2] - mn1);
                float p3 = __expf(s[nt][3] - mn1);
                sum0 += p0 + p1;
                sum1 += p2 + p3;
                pk[nt][0] = packh2(p0, p1);
                pk[nt][1] = packh2(p2, p3);
            }
            sum0 += __shfl_xor_sync(0xffffffffu, sum0, 1);
            sum0 += __shfl_xor_sync(0xffffffffu, sum0, 2);
            sum1 += __shfl_xor_sync(0xffffffffu, sum1, 1);
            sum1 += __shfl_xor_sync(0xffffffffu, sum1, 2);

            l0 = l0 * al0 + sum0;
            l1 = l1 * al1 + sum1;
            m0 = mn0; m1 = mn1;

#pragma unroll
            for (int nt = 0; nt < 10; nt++) {
                oacc[nt][0] *= al0; oacc[nt][1] *= al0;
                oacc[nt][2] *= al1; oacc[nt][3] *= al1;
            }

#pragma unroll
            for (int j = 0; j < 4; j++) {
                const unsigned fa0 = pk[2*j][0],   fa1 = pk[2*j][1];
                const unsigned fa2 = pk[2*j+1][0], fa3 = pk[2*j+1][1];
#pragma unroll
                for (int p = 0; p < 5; p++) {
                    unsigned bq[4];
                    ldsm_x4t(bq, &cV[(hv * 64 + j * 16 + (lane & 15)) * QPITCH
                                     + p * 16 + ((lane >> 4) & 1) * 8]);
                    mma_f16(oacc[2*p][0], oacc[2*p][1], oacc[2*p][2], oacc[2*p][3],
                            fa0, fa1, fa2, fa3, bq[0], bq[1]);
                    mma_f16(oacc[2*p+1][0], oacc[2*p+1][1], oacc[2*p+1][2], oacc[2*p+1][3],
                            fa0, fa1, fa2, fa3, bq[2], bq[3]);
                }
            }
        }
    }

    const float inv0 = 1.0f / l0, inv1 = 1.0f / l1;
    const int r0 = qbase + w * 16 + (lane >> 2);
#pragma unroll
    for (int nt = 0; nt < 10; nt++) {
        const int c = h * HD + nt * 8 + (lane & 3) * 2;
        *(__half2*)&attn_out[(size_t)r0 * HID + c] =
            __floats2half2_rn(oacc[nt][0] * inv0, oacc[nt][1] * inv0);
        *(__half2*)&attn_out[(size_t)(r0 + 8) * HID + c] =
            __floats2half2_rn(oacc[nt][2] * inv1, oacc[nt][3] * inv1);
    }
}

// ---------------- launch ----------------
extern "C" void kernel_launch(void* const* d_in, const int* in_sizes, int n_in,
                              void* d_out, int out_size)
{
    const float* hidden = (const float*)d_in[0];
    const float* cosp   = (const float*)d_in[1];
    const float* sinp   = (const float*)d_in[2];
    const float* w_qkv  = (const float*)d_in[3];
    const float* b_qkv  = (const float*)d_in[4];
    const float* w_proj = (const float*)d_in[5];
    const float* b_proj = (const float*)d_in[6];

    __half *q_p, *k_p, *v_p, *attn16_p, *a16_p, *wqkv16_p, *wpr16_p;
    float  *bqkv_p;
    cudaGetSymbolAddress((void**)&q_p, g_q);
    cudaGetSymbolAddress((void**)&k_p, g_k);
    cudaGetSymbolAddress((void**)&v_p, g_v);
    cudaGetSymbolAddress((void**)&attn16_p, g_attn16);
    cudaGetSymbolAddress((void**)&a16_p, g_a16);
    cudaGetSymbolAddress((void**)&wqkv16_p, g_wqkv16);
    cudaGetSymbolAddress((void**)&bqkv_p, g_bqkv);
    cudaGetSymbolAddress((void**)&wpr16_p, g_wpr16);

    cudaFuncSetAttribute(fattn_kernel,
                         cudaFuncAttributeMaxDynamicSharedMemorySize, ATTN_SMEM);
    cudaFuncSetAttribute(hgemm_qkv,
                         cudaFuncAttributeMaxDynamicSharedMemorySize, GEMM_SMEM);
    cudaFuncSetAttribute(hgemm_f32,
                         cudaFuncAttributeMaxDynamicSharedMemorySize, GEMM_SMEM);

    // 0) merged prep
    prep_kernel<<<PREP_NA + PREP_NB + PREP_NC, 256>>>(
        hidden, w_qkv, b_qkv, w_proj, a16_p, wqkv16_p, bqkv_p, wpr16_p);

    // 1) QKV GEMM with fused RoPE (3-stage pipeline)
    hgemm_qkv<<<dim3(QKVN / 128, SEQ / 128), 256, GEMM_SMEM>>>(
        a16_p, wqkv16_p, bqkv_p, cosp, sinp, q_p, k_p, v_p, QKVN, HID);

    // 2) flash attention (block-diagonal)
    fattn_kernel<<<dim3(NSEG * 4, NHEAD), 256, ATTN_SMEM>>>(
        q_p, k_p, v_p, attn16_p);

    // 3) proj GEMM (3-stage pipeline, fp32 out)
    hgemm_f32<<<dim3(HID / 128, SEQ / 128), 256, GEMM_SMEM>>>(
        attn16_p, wpr16_p, b_proj, (float*)d_out, HID, HID);
}

// round 15
// speedup vs baseline: 1.0370x; 1.0370x over previous
#include <cuda_runtime.h>
#include <cuda_fp16.h>
#include <cstdint>

#define SEQ    3072
#define HID    1280
#define NHEAD  16
#define HD     80
#define SEGLEN 512
#define NSEG   6
#define QKVN   3840

// ---------------- scratch (no allocations allowed) ----------------
// q/k stored in INTERLEAVED-PAIR dim order (2d, 2d+1) = rotated (d, d+40);
// QK^T is invariant since q and k share the permutation. v in true order.
__device__ __half g_q[NHEAD * SEQ * HD];
__device__ __half g_k[NHEAD * SEQ * HD];
__device__ __half g_v[NHEAD * SEQ * HD];
__device__ __half g_attn16[SEQ * HID];

__device__ __half g_a16[SEQ * HID];
__device__ __half g_wqkv16[QKVN * HID];        // Q/K rows permuted (rope pairs adjacent)
__device__ float  g_bqkv[QKVN];
__device__ __half g_wpr16[HID * HID];

// ---------------- helpers ----------------
__device__ __forceinline__ void cp16(void* dst, const void* src)
{
    unsigned d = (unsigned)__cvta_generic_to_shared(dst);
    asm volatile("cp.async.cg.shared.global [%0], [%1], 16;" :: "r"(d), "l"(src));
}

__device__ __forceinline__ void mma_f16(
    float& c0, float& c1, float& c2, float& c3,
    unsigned a0, unsigned a1, unsigned a2, unsigned a3,
    unsigned b0, unsigned b1)
{
    asm volatile(
        "mma.sync.aligned.m16n8k16.row.col.f32.f16.f16.f32 "
        "{%0,%1,%2,%3}, {%4,%5,%6,%7}, {%8,%9}, {%0,%1,%2,%3};"
        : "+f"(c0), "+f"(c1), "+f"(c2), "+f"(c3)
        : "r"(a0), "r"(a1), "r"(a2), "r"(a3), "r"(b0), "r"(b1));
}

__device__ __forceinline__ void ldsm_x4(unsigned* r, const void* p)
{
    unsigned addr = (unsigned)__cvta_generic_to_shared(p);
    asm volatile("ldmatrix.sync.aligned.m8n8.x4.shared.b16 {%0,%1,%2,%3}, [%4];"
                 : "=r"(r[0]), "=r"(r[1]), "=r"(r[2]), "=r"(r[3]) : "r"(addr));
}
__device__ __forceinline__ void ldsm_x4t(unsigned* r, const void* p)
{
    unsigned addr = (unsigned)__cvta_generic_to_shared(p);
    asm volatile("ldmatrix.sync.aligned.m8n8.x4.trans.shared.b16 {%0,%1,%2,%3}, [%4];"
                 : "=r"(r[0]), "=r"(r[1]), "=r"(r[2]), "=r"(r[3]) : "r"(addr));
}

__device__ __forceinline__ unsigned packh2(float a, float b)
{
    __half2 h = __floats2half2_rn(a, b);
    return *(unsigned*)&h;
}

// ---------------- merged prep kernel (all casts in one launch) ----------------
#define PREP_NA ((SEQ * HID / 4) / 256)          // 3840
#define PREP_NB ((QKVN * HID / 4) / 256)         // 4800
#define PREP_NC ((HID * HID / 4) / 256)          // 1600

__global__ __launch_bounds__(256) void prep_kernel(
    const float* __restrict__ hidden, const float* __restrict__ w_qkv,
    const float* __restrict__ b_qkv,  const float* __restrict__ w_proj,
    __half* __restrict__ a16, __half* __restrict__ wqkv16,
    float* __restrict__ bqkv, __half* __restrict__ wpr16)
{
    const int gb = blockIdx.x;
    if (gb < PREP_NA) {
        int i = gb * 256 + threadIdx.x;
        float4 x = ((const float4*)hidden)[i];
        ((__half2*)a16)[i * 2]     = __floats2half2_rn(x.x, x.y);
        ((__half2*)a16)[i * 2 + 1] = __floats2half2_rn(x.z, x.w);
    } else if (gb < PREP_NA + PREP_NB) {
        if (gb == PREP_NA) {
            for (int n = threadIdx.x; n < QKVN; n += 256) {
                int reg = n / HID, cc = n % HID;
                int h = cc / 80, j = cc % 80;
                int old = (reg < 2) ? reg * HID + h * 80 + (j >> 1) + (j & 1) * 40 : n;
                bqkv[n] = b_qkv[old];
            }
        }
        int i = (gb - PREP_NA) * 256 + threadIdx.x;
        int nr   = i / (HID / 4);
        int col4 = (i % (HID / 4)) * 4;
        int reg = nr / HID, cc = nr % HID;
        int h = cc / 80, j = cc % 80;
        int old = (reg < 2) ? reg * HID + h * 80 + (j >> 1) + (j & 1) * 40 : nr;
        float4 x = *(const float4*)&w_qkv[(size_t)old * HID + col4];
        __half2* o = (__half2*)&wqkv16[(size_t)nr * HID + col4];
        o[0] = __floats2half2_rn(x.x, x.y);
        o[1] = __floats2half2_rn(x.z, x.w);
    } else {
        int i = (gb - PREP_NA - PREP_NB) * 256 + threadIdx.x;
        float4 x = ((const float4*)w_proj)[i];
        ((__half2*)wpr16)[i * 2]     = __floats2half2_rn(x.x, x.y);
        ((__half2*)wpr16)[i * 2 + 1] = __floats2half2_rn(x.z, x.w);
    }
}

// ---------------- GEMM config: 128x128 tiles, 8 warps, 64x32 warp tile, BK=64 ----------------
// 2-stage cp.async pipeline, single barrier per k-chunk (R13 config),
// PERSISTENT CTAs looping over tiles (kills wave quantization).
#define SPAD 72
#define GSTG (128 * SPAD)
#define GEMM_SMEM (4 * GSTG * 2)   // 73728 B
#define GEMM_GRID 296              // 2 CTAs/SM x 148 SMs

#define PFG(k0, s) do {                                                  \
        const int st = (s) * GSTG;                                       \
        for (int i = t; i < 1024; i += 256) {                            \
            int r = i >> 3, c8 = (i & 7) * 8;                            \
            cp16(sA + st + r * SPAD + c8, A + (size_t)(bm + r) * K + (k0) + c8); \
            cp16(sB + st + r * SPAD + c8, B + (size_t)(bn + r) * K + (k0) + c8); \
        }                                                                \
        asm volatile("cp.async.commit_group;");                          \
    } while (0)

#define GEMM_MAINLOOP()                                                  \
    PFG(0, 0);                                                           \
    int s = 0;                                                           \
    for (int k0 = 0; k0 < K; k0 += 64, s ^= 1) {                         \
        asm volatile("cp.async.wait_group 0;");                          \
        __syncthreads();                                                 \
        if (k0 + 64 < K) PFG(k0 + 64, s ^ 1);                            \
        const int st = s * GSTG;                                         \
        _Pragma("unroll")                                                \
        for (int ks = 0; ks < 64; ks += 16) {                            \
            unsigned af[4][4], bq[2][4];                                 \
            _Pragma("unroll")                                            \
            for (int p = 0; p < 2; p++)                                  \
                ldsm_x4(bq[p], &sB[st + (nw * 32 + p * 16 + b_row4) * SPAD + ks + b_col4]); \
            _Pragma("unroll")                                            \
            for (int mt = 0; mt < 4; mt++)                               \
                ldsm_x4(af[mt], &sA[st + (mw * 64 + mt * 16 + a_row) * SPAD + ks + a_col]); \
            _Pragma("unroll")                                            \
            for (int mt = 0; mt < 4; mt++)                               \
                _Pragma("unroll")                                        \
                for (int p = 0; p < 2; p++) {                            \
                    mma_f16(acc[mt][2*p][0], acc[mt][2*p][1], acc[mt][2*p][2], acc[mt][2*p][3], \
                            af[mt][0], af[mt][1], af[mt][2], af[mt][3],  \
                            bq[p][0], bq[p][1]);                         \
                    mma_f16(acc[mt][2*p+1][0], acc[mt][2*p+1][1], acc[mt][2*p+1][2], acc[mt][2*p+1][3], \
                            af[mt][0], af[mt][1], af[mt][2], af[mt][3],  \
                            bq[p][2], bq[p][3]);                         \
                }                                                        \
        }                                                                \
    }

#define GEMM_PROLOG()                                                    \
    extern __shared__ __half smg[];                                      \
    __half* sA = smg;                                                    \
    __half* sB = smg + 2 * GSTG;                                         \
    const int t    = threadIdx.x;                                        \
    const int lane = t & 31;                                             \
    const int warp = t >> 5;                                             \
    const int mw   = warp >> 2;                                          \
    const int nw   = warp & 3;                                           \
    const int a_row  = (lane & 15);                                      \
    const int a_col  = (lane >> 4) * 8;                                  \
    const int b_row4 = (lane & 7) + ((lane >> 4) & 1) * 8;               \
    const int b_col4 = ((lane >> 3) & 1) * 8;

#define ACC_INIT()                                                       \
    float acc[4][4][4];                                                  \
    _Pragma("unroll")                                                    \
    for (int i = 0; i < 4; i++)                                          \
        _Pragma("unroll")                                                \
        for (int j = 0; j < 4; j++)                                      \
            _Pragma("unroll")                                            \
            for (int e = 0; e < 4; e++) acc[i][j][e] = 0.0f;

// ---------------- QKV GEMM with fused RoPE (persistent, coalesced stores) ----------------
__global__ __launch_bounds__(256, 2) void hgemm_qkv(
    const __half* __restrict__ A, const __half* __restrict__ B,
    const float* __restrict__ bias,
    const float* __restrict__ cosp, const float* __restrict__ sinp,
    __half* __restrict__ q, __half* __restrict__ k, __half* __restrict__ v,
    int M, int N, int K)
{
    GEMM_PROLOG();
    const int ntx = N / 128;
    const int ntiles = ntx * (M / 128);

    for (int tile = blockIdx.x; tile < ntiles; tile += gridDim.x) {
        const int bm = (tile / ntx) * 128;
        const int bn = (tile % ntx) * 128;
        ACC_INIT();
        GEMM_MAINLOOP();

#pragma unroll
        for (int mt = 0; mt < 4; mt++) {
            const int r0 = bm + mw * 64 + mt * 16 + (lane >> 2);
            const int r1 = r0 + 8;
#pragma unroll
            for (int nt = 0; nt < 4; nt++) {
                const int c = bn + nw * 32 + nt * 8 + (lane & 3) * 2;
                const float bv0 = bias[c], bv1 = bias[c + 1];
                const float a0 = acc[mt][nt][0] + bv0, a1 = acc[mt][nt][1] + bv1;
                const float a2 = acc[mt][nt][2] + bv0, a3 = acc[mt][nt][3] + bv1;
                if (c < 2560) {
                    const int cc = (c < HID) ? c : c - HID;
                    __half* dst = (c < HID) ? q : k;
                    const int h  = cc / 80;
                    const int jj = cc % 80;
                    const int d  = jj >> 1;
                    {
                        const float co = cosp[r0 * HD + d], sn = sinp[r0 * HD + d];
                        *(__half2*)&dst[(h * SEQ + r0) * HD + jj] =
                            __floats2half2_rn(a0 * co - a1 * sn, a1 * co + a0 * sn);
                    }
                    {
                        const float co = cosp[r1 * HD + d], sn = sinp[r1 * HD + d];
                        *(__half2*)&dst[(h * SEQ + r1) * HD + jj] =
                            __floats2half2_rn(a2 * co - a3 * sn, a3 * co + a2 * sn);
                    }
                } else {
                    const int cc = c - 2560;
                    const int h = cc / 80, j = cc % 80;
                    *(__half2*)&v[(h * SEQ + r0) * HD + j] = __floats2half2_rn(a0, a1);
                    *(__half2*)&v[(h * SEQ + r1) * HD + j] = __floats2half2_rn(a2, a3);
                }
            }
        }
    }
}

// ---------------- plain GEMM (proj): fp32 out, persistent ----------------
__global__ __launch_bounds__(256, 2) void hgemm_f32(
    const __half* __restrict__ A, const __half* __restrict__ B,
    const float* __restrict__ bias, float* __restrict__ C,
    int M, int N, int K)
{
    GEMM_PROLOG();
    const int ntx = N / 128;
    const int ntiles = ntx * (M / 128);

    for (int tile = blockIdx.x; tile < ntiles; tile += gridDim.x) {
        const int bm = (tile / ntx) * 128;
        const int bn = (tile % ntx) * 128;
        ACC_INIT();
        GEMM_MAINLOOP();

#pragma unroll
        for (int mt = 0; mt < 4; mt++) {
            const int r0 = bm + mw * 64 + mt * 16 + (lane >> 2);
            const int r1 = r0 + 8;
#pragma unroll
            for (int nt = 0; nt < 4; nt++) {
                const int c = bn + nw * 32 + nt * 8 + (lane & 3) * 2;
                const float bv0 = bias[c], bv1 = bias[c + 1];
                float2 o0 = {acc[mt][nt][0] + bv0, acc[mt][nt][1] + bv1};
                float2 o1 = {acc[mt][nt][2] + bv0, acc[mt][nt][3] + bv1};
                *(float2*)&C[(size_t)r0 * N + c] = o0;
                *(float2*)&C[(size_t)r1 * N + c] = o1;
            }
        }
    }
}

// ---------------- flash attention (unchanged R13) ----------------
#define QPITCH 88
#define TILE_H (128 * QPITCH)
#define ATTN_SMEM (5 * TILE_H * 2)

__global__ __launch_bounds__(256, 2) void fattn_kernel(
    const __half* __restrict__ q, const __half* __restrict__ k,
    const __half* __restrict__ v, __half* __restrict__ attn_out)
{
    extern __shared__ char smraw[];
    __half* sQ = (__half*)smraw;
    __half* sK[2] = {sQ + TILE_H,     sQ + 2 * TILE_H};
    __half* sV[2] = {sQ + 3 * TILE_H, sQ + 4 * TILE_H};

    const int tid  = threadIdx.x;
    const int lane = tid & 31;
    const int w    = tid >> 5;
    const int h    = blockIdx.y;
    const int seg  = blockIdx.x >> 2;
    const int qc   = blockIdx.x & 3;
    const int qbase = seg * SEGLEN + qc * 128;
    const int kbase = seg * SEGLEN;
    const float scale = 0.11180339887498949f;

    const int a_row  = (lane & 15);
    const int a_col  = (lane >> 4) * 8;
    const int b_row4 = (lane & 7) + ((lane >> 4) & 1) * 8;
    const int b_col4 = ((lane >> 3) & 1) * 8;

    for (int i = tid; i < 1280; i += 256) {
        int r = i / 10, c8 = (i % 10) * 8;
        cp16(&sQ[r * QPITCH + c8],    &q[(size_t)(h * SEQ + qbase + r) * HD + c8]);
        cp16(&sK[0][r * QPITCH + c8], &k[(size_t)(h * SEQ + kbase + r) * HD + c8]);
        cp16(&sV[0][r * QPITCH + c8], &v[(size_t)(h * SEQ + kbase + r) * HD + c8]);
    }
    asm volatile("cp.async.commit_group;");

    float m0 = -1e30f, m1 = -1e30f, l0 = 0.0f, l1 = 0.0f;
    float oacc[10][4];
#pragma unroll
    for (int nt = 0; nt < 10; nt++)
#pragma unroll
        for (int e = 0; e < 4; e++) oacc[nt][e] = 0.0f;

    for (int kt = 0; kt < 4; kt++) {
        asm volatile("cp.async.wait_group 0;");
        __syncthreads();
        if (kt < 3) {
            const int nb = (kt + 1) & 1;
            for (int i = tid; i < 1280; i += 256) {
                int r = i / 10, c8 = (i % 10) * 8;
                cp16(&sK[nb][r * QPITCH + c8],
                     &k[(size_t)(h * SEQ + kbase + (kt + 1) * 128 + r) * HD + c8]);
                cp16(&sV[nb][r * QPITCH + c8],
                     &v[(size_t)(h * SEQ + kbase + (kt + 1) * 128 + r) * HD + c8]);
            }
            asm volatile("cp.async.commit_group;");
        }
        __half* cK = sK[kt & 1];
        __half* cV = sV[kt & 1];

#pragma unroll
        for (int hv = 0; hv < 2; hv++) {
            float s[8][4];
#pragma unroll
            for (int nt = 0; nt < 8; nt++)
#pragma unroll
                for (int e = 0; e < 4; e++) s[nt][e] = 0.0f;

#pragma unroll
            for (int ks = 0; ks < 80; ks += 16) {
                unsigned af[4];
                ldsm_x4(af, &sQ[(w * 16 + a_row) * QPITCH + ks + a_col]);
#pragma unroll
                for (int p = 0; p < 4; p++) {
                    unsigned bq[4];
                    ldsm_x4(bq, &cK[(hv * 64 + p * 16 + b_row4) * QPITCH + ks + b_col4]);
                    mma_f16(s[2*p][0], s[2*p][1], s[2*p][2], s[2*p][3],
                            af[0], af[1], af[2], af[3], bq[0], bq[1]);
                    mma_f16(s[2*p+1][0], s[2*p+1][1], s[2*p+1][2], s[2*p+1][3],
                            af[0], af[1], af[2], af[3], bq[2], bq[3]);
                }
            }

            float mx0 = -1e30f, mx1 = -1e30f;
#pragma unroll
            for (int nt = 0; nt < 8; nt++) {
                s[nt][0] *= scale; s[nt][1] *= scale;
                s[nt][2] *= scale; s[nt][3] *= scale;
                mx0 = fmaxf(mx0, fmaxf(s[nt][0], s[nt][1]));
                mx1 = fmaxf(mx1, fmaxf(s[nt][2], s[nt][3]));
            }
            mx0 = fmaxf(mx0, __shfl_xor_sync(0xffffffffu, mx0, 1));
            mx0 = fmaxf(mx0, __shfl_xor_sync(0xffffffffu, mx0, 2));
            mx1 = fmaxf(mx1, __shfl_xor_sync(0xffffffffu, mx1, 1));
            mx1 = fmaxf(mx1, __shfl_xor_sync(0xffffffffu, mx1, 2));

            const float mn0 = fmaxf(m0, mx0), mn1 = fmaxf(m1, mx1);
            const float al0 = __expf(m0 - mn0), al1 = __expf(m1 - mn1);

            float sum0 = 0.0f, sum1 = 0.0f;
            unsigned pk[8][2];
#pragma unroll
            for (int nt = 0; nt < 8; nt++) {
                float p0 = __expf(s[nt][0] - mn0);
                float p1 = __expf(s[nt][1] - mn0);
                float p2 = __expf(s[nt][2] - mn1);
                float p3 = __expf(s[nt][3] - mn1);
                sum0 += p0 + p1;
                sum1 += p2 + p3;
                pk[nt][0] = packh2(p0, p1);
                pk[nt][1] = packh2(p2, p3);
            }
            sum0 += __shfl_xor_sync(0xffffffffu, sum0, 1);
            sum0 += __shfl_xor_sync(0xffffffffu, sum0, 2);
            sum1 += __shfl_xor_sync(0xffffffffu, sum1, 1);
            sum1 += __shfl_xor_sync(0xffffffffu, sum1, 2);

            l0 = l0 * al0 + sum0;
            l1 = l1 * al1 + sum1;
            m0 = mn0; m1 = mn1;

#pragma unroll
            for (int nt = 0; nt < 10; nt++) {
                oacc[nt][0] *= al0; oacc[nt][1] *= al0;
                oacc[nt][2] *= al1; oacc[nt][3] *= al1;
            }

#pragma unroll
            for (int j = 0; j < 4; j++) {
                const unsigned fa0 = pk[2*j][0],   fa1 = pk[2*j][1];
                const unsigned fa2 = pk[2*j+1][0], fa3 = pk[2*j+1][1];
#pragma unroll
                for (int p = 0; p < 5; p++) {
                    unsigned bq[4];
                    ldsm_x4t(bq, &cV[(hv * 64 + j * 16 + (lane & 15)) * QPITCH
                                     + p * 16 + ((lane >> 4) & 1) * 8]);
                    mma_f16(oacc[2*p][0], oacc[2*p][1], oacc[2*p][2], oacc[2*p][3],
                            fa0, fa1, fa2, fa3, bq[0], bq[1]);
                    mma_f16(oacc[2*p+1][0], oacc[2*p+1][1], oacc[2*p+1][2], oacc[2*p+1][3],
                            fa0, fa1, fa2, fa3, bq[2], bq[3]);
                }
            }
        }
    }

    const float inv0 = 1.0f / l0, inv1 = 1.0f / l1;
    const int r0 = qbase + w * 16 + (lane >> 2);
#pragma unroll
    for (int nt = 0; nt < 10; nt++) {
        const int c = h * HD + nt * 8 + (lane & 3) * 2;
        *(__half2*)&attn_out[(size_t)r0 * HID + c] =
            __floats2half2_rn(oacc[nt][0] * inv0, oacc[nt][1] * inv0);
        *(__half2*)&attn_out[(size_t)(r0 + 8) * HID + c] =
            __floats2half2_rn(oacc[nt][2] * inv1, oacc[nt][3] * inv1);
    }
}

// ---------------- launch ----------------
extern "C" void kernel_launch(void* const* d_in, const int* in_sizes, int n_in,
                              void* d_out, int out_size)
{
    const float* hidden = (const float*)d_in[0];
    const float* cosp   = (const float*)d_in[1];
    const float* sinp   = (const float*)d_in[2];
    const float* w_qkv  = (const float*)d_in[3];
    const float* b_qkv  = (const float*)d_in[4];
    const float* w_proj = (const float*)d_in[5];
    const float* b_proj = (const float*)d_in[6];

    __half *q_p, *k_p, *v_p, *attn16_p, *a16_p, *wqkv16_p, *wpr16_p;
    float  *bqkv_p;
    cudaGetSymbolAddress((void**)&q_p, g_q);
    cudaGetSymbolAddress((void**)&k_p, g_k);
    cudaGetSymbolAddress((void**)&v_p, g_v);
    cudaGetSymbolAddress((void**)&attn16_p, g_attn16);
    cudaGetSymbolAddress((void**)&a16_p, g_a16);
    cudaGetSymbolAddress((void**)&wqkv16_p, g_wqkv16);
    cudaGetSymbolAddress((void**)&bqkv_p, g_bqkv);
    cudaGetSymbolAddress((void**)&wpr16_p, g_wpr16);

    cudaFuncSetAttribute(fattn_kernel,
                         cudaFuncAttributeMaxDynamicSharedMemorySize, ATTN_SMEM);
    cudaFuncSetAttribute(hgemm_qkv,
                         cudaFuncAttributeMaxDynamicSharedMemorySize, GEMM_SMEM);
    cudaFuncSetAttribute(hgemm_f32,
                         cudaFuncAttributeMaxDynamicSharedMemorySize, GEMM_SMEM);

    // 0) merged prep
    prep_kernel<<<PREP_NA + PREP_NB + PREP_NC, 256>>>(
        hidden, w_qkv, b_qkv, w_proj, a16_p, wqkv16_p, bqkv_p, wpr16_p);

    // 1) QKV GEMM with fused RoPE (persistent: 296 CTAs over 720 tiles)
    hgemm_qkv<<<GEMM_GRID, 256, GEMM_SMEM>>>(
        a16_p, wqkv16_p, bqkv_p, cosp, sinp, q_p, k_p, v_p, SEQ, QKVN, HID);

    // 2) flash attention (block-diagonal)
    fattn_kernel<<<dim3(NSEG * 4, NHEAD), 256, ATTN_SMEM>>>(
        q_p, k_p, v_p, attn16_p);

    // 3) proj GEMM (240 tiles, single wave)
    hgemm_f32<<<240, 256, GEMM_SMEM>>>(
        attn16_p, wpr16_p, b_proj, (float*)d_out, SEQ, HID, HID);
}